// round 15
// baseline (speedup 1.0000x reference)
#include <cuda_runtime.h>
#include <cstdint>

#define D 8192
#define B 8
#define NBLK 256
#define CPACK 2262.7417f             // 25 * sqrt(8192): pack target rms = 25

// Static device scratch (no runtime allocation allowed).
__device__ __align__(128) unsigned g_M8[(size_t)D * D / 4];  // 64 MB s8 M, pair-fragment-linear
__device__ __align__(128) unsigned g_M4[(size_t)D * D / 8];  // 32 MB s4 M (nibble-packed pairs)
__device__ __align__(16) float    g_u[2][B * D];             // ping-pong fp32 state
__device__ __align__(16) float    g_part[2][NBLK][B];        // per-block row sum(val^2)
__device__ __align__(16) unsigned g_hb8[2][(D / 32) * 64];   // double-buffered s8 B-fragments
__device__ int      g_sums16[16][B];                         // per-step Σ q_h (zero-point)
__device__ unsigned g_bar;                                   // grid barrier counter

// ---------------------------------------------------------------------------
// Primitives
// ---------------------------------------------------------------------------
__device__ __forceinline__ void mma_s8(int* d, const uint4& a, unsigned b0, unsigned b1) {
    asm volatile(
        "mma.sync.aligned.m16n8k32.row.col.s32.s8.s8.s32 "
        "{%0,%1,%2,%3},{%4,%5,%6,%7},{%8,%9},{%0,%1,%2,%3};"
        : "+r"(d[0]), "+r"(d[1]), "+r"(d[2]), "+r"(d[3])
        : "r"(a.x), "r"(a.y), "r"(a.z), "r"(a.w), "r"(b0), "r"(b1));
}
__device__ __forceinline__ void ldg_v8_el(const unsigned* p, uint4& a, uint4& b) {
    asm volatile(
        "ld.global.nc.L2::evict_last.v8.b32 {%0,%1,%2,%3,%4,%5,%6,%7}, [%8];"
        : "=r"(a.x), "=r"(a.y), "=r"(a.z), "=r"(a.w),
          "=r"(b.x), "=r"(b.y), "=r"(b.z), "=r"(b.w) : "l"(p));
}
__device__ __forceinline__ unsigned sx4(unsigned t) {        // nibble sign-extend
    return __vsub4(t ^ 0x08080808u, 0x08080808u);
}
__device__ __forceinline__ unsigned pack_nib(unsigned a, unsigned b) {
    unsigned ta = __vaddss4(a, 0x08080808u);
    unsigned tb = __vaddss4(b, 0x08080808u);
    return ((ta >> 4) & 0x0F0F0F0Fu) | (tb & 0xF0F0F0F0u);
}
// L1-bypassing loads for cross-block data (L1 is stale-unsafe within a launch)
__device__ __forceinline__ float ldcg_f(const float* p) {
    float v; asm volatile("ld.global.cg.f32 %0, [%1];" : "=f"(v) : "l"(p)); return v;
}
__device__ __forceinline__ int ldcg_i(const int* p) {
    int v; asm volatile("ld.global.cg.s32 %0, [%1];" : "=r"(v) : "l"(p)); return v;
}
__device__ __forceinline__ uint2 ldcg_u2(const void* p) {
    uint2 v; asm volatile("ld.global.cg.v2.u32 {%0,%1}, [%2];"
                          : "=r"(v.x), "=r"(v.y) : "l"(p)); return v;
}

// ---------------------------------------------------------------------------
// One-time: M fp32 -> s8 (pair-fragment-linear, verified R7..R14) AND nibble
// s4 in one pass. Block = one cg-PAIR (64 i-rows) x 128 j. Word layout:
// W(cg, jt, L, r) = cg*65536 + (jt>>1)*256 + L*8 + (jt&1)*4 + r; s4 word at
// (cg4=cg/2, off) packs (even cg lo-nibbles, odd cg hi-nibbles).
// ---------------------------------------------------------------------------
__global__ void convert_kernel(const float* __restrict__ M) {
    __shared__ char     tq[64 * 128];
    __shared__ unsigned sW[2][1024];
    const int tid = threadIdx.x;                 // 256
    const int cp  = blockIdx.x & 127;            // cg-pair 0..127
    const int bj  = blockIdx.x >> 7;             // j-super 0..63 (128 j each)
    const int i0  = cp * 64, j0 = bj * 128;

    const float4* M4p = (const float4*)M;
#pragma unroll
    for (int rep = 0; rep < 8; rep++) {
        int idx = rep * 256 + tid;               // 2048 float4 = 64 x 128 floats
        int r = idx >> 5, c4 = idx & 31;
        float4 v = M4p[(size_t)(i0 + r) * (D / 4) + (j0 >> 2) + c4];
        float vv[4] = {v.x, v.y, v.z, v.w};
#pragma unroll
        for (int e = 0; e < 4; e++) {
            int q = __float2int_rn(fmaf(vv[e], 255.f, -127.5f));
            q = max(-128, min(127, q));
            tq[r * 128 + c4 * 4 + e] = (char)q;
        }
    }
    __syncthreads();

#pragma unroll
    for (int wrep = 0; wrep < 8; wrep++) {
        int widx = wrep * 256 + tid;             // 2048 s8 words (2 cg x 1024)
        int cgl = widx >> 10;
        int wi2 = widx & 1023;
        int tl = wi2 >> 7, wi = wi2 & 127;
        int Lq = wi >> 2, rq = wi & 3;
        int jloc = (Lq >> 2) + 8 * (rq & 1);
        int kb   = 4 * (Lq & 3) + 16 * (rq >> 1) + cgl * 32;
        unsigned wd = ((unsigned char)tq[(kb + 0) * 128 + tl * 16 + jloc])
                    | ((unsigned char)tq[(kb + 1) * 128 + tl * 16 + jloc] << 8)
                    | ((unsigned char)tq[(kb + 2) * 128 + tl * 16 + jloc] << 16)
                    | ((unsigned char)tq[(kb + 3) * 128 + tl * 16 + jloc] << 24);
        int jt = bj * 8 + tl;
        size_t off = (size_t)(jt >> 1) * 256 + Lq * 8 + (jt & 1) * 4 + rq;
        g_M8[(size_t)(cp * 2 + cgl) * 65536 + off] = wd;
        sW[cgl][tl * 128 + wi] = wd;
    }
    __syncthreads();

#pragma unroll
    for (int wrep = 0; wrep < 4; wrep++) {
        int widx = wrep * 256 + tid;             // 1024 s4 words
        int tl = widx >> 7, wi = widx & 127;
        int Lq = wi >> 2, rq = wi & 3;
        int jt = bj * 8 + tl;
        size_t off = (size_t)(jt >> 1) * 256 + Lq * 8 + (jt & 1) * 4 + rq;
        g_M4[(size_t)cp * 65536 + off] =
            pack_nib(sW[0][tl * 128 + wi], sW[1][tl * 128 + wi]);
    }
}

// ---------------------------------------------------------------------------
// One-time prep (8 blocks, one per row): x -> g_u[0]; quantize x -> g_hb8[0]
// (exact scale CPACK/||x_b||); Σq -> g_sums16[0][b]; zero g_sums16[1..15],
// g_part[0], g_bar.
// ---------------------------------------------------------------------------
__global__ void prep_kernel(const float* __restrict__ x) {
    const int b = blockIdx.x, tid = threadIdx.x;  // 8 x 256
    __shared__ float red[8];
    __shared__ float s_sh, s_tot;
    __shared__ int   ired[8];

    float ss = 0.f;
    for (int i = tid; i < D; i += 256) {
        float v = x[b * D + i];
        g_u[0][b * D + i] = v;
        ss = fmaf(v, v, ss);
    }
#pragma unroll
    for (int o = 16; o; o >>= 1) ss += __shfl_down_sync(0xFFFFFFFFu, ss, o);
    if ((tid & 31) == 0) red[tid >> 5] = ss;
    __syncthreads();
    if (tid == 0) {
        float tot = 0.f;
#pragma unroll
        for (int w = 0; w < 8; w++) tot += red[w];
        s_tot = tot;
        s_sh  = CPACK * rsqrtf(fmaxf(tot, 1e-30f));
    }
    __syncthreads();
    const float s = s_sh;

    // quantize: thread t owns i in [32t, 32t+32); word t*64 + b*8 + (g&3)*2+(g>>2)
    int qsum = 0;
    const float4* x4 = (const float4*)(x + (size_t)b * D);
#pragma unroll
    for (int g = 0; g < 8; g++) {
        float4 v = x4[tid * 8 + g];
        float vv[4] = {v.x, v.y, v.z, v.w};
        unsigned wd = 0;
#pragma unroll
        for (int e = 0; e < 4; e++) {
            int q = __float2int_rn(vv[e] * s);
            q = max(-127, min(127, q));
            qsum += q;
            wd |= (unsigned)(q & 255) << (8 * e);
        }
        g_hb8[0][tid * 64 + b * 8 + (g & 3) * 2 + (g >> 2)] = wd;
    }
#pragma unroll
    for (int o = 16; o; o >>= 1) qsum += __shfl_down_sync(0xFFFFFFFFu, qsum, o);
    if ((tid & 31) == 0) ired[tid >> 5] = qsum;
    __syncthreads();
    if (tid == 0) {
        int t = 0;
#pragma unroll
        for (int w = 0; w < 8; w++) t += ired[w];
        g_sums16[0][b] = t;
#pragma unroll
        for (int k = 1; k < 16; k++) g_sums16[k][b] = 0;
        if (b == 0) g_bar = 0;
    }
    g_part[0][tid][b] = (tid == 0) ? s_tot : 0.f;
}

// ---------------------------------------------------------------------------
// Persistent kernel: all 16 homogeneous steps. Grid 256 x 512 (2 CTAs/SM
// guaranteed -> all blocks co-resident; hand-rolled grid barrier is safe).
// Per step: mainloop (s4 steps 0..14 / s8 step 15) -> split-K -> epilogue
// (val in regs; write g_u + norm partials) -> barrier -> derive next scale
// (fixed-order gather, deterministic) + quantize val into other g_hb8 buffer
// + int-atomic Σq -> barrier. Cross-block reads use ld.cg (L1 stale-unsafe).
// ---------------------------------------------------------------------------
__global__ void __launch_bounds__(512, 2)
attractor_kernel(const float* __restrict__ hs_in) {
    __shared__ int   redH[16 * 256];
    __shared__ float sPart[512];
    __shared__ float sScale[8];
    const int tid = threadIdx.x;
    const int L   = tid & 31;
    const int w   = tid >> 5;          // 0..15
    const int jp  = blockIdx.x;        // j-tile pair
    const int jb  = jp * 32;
    unsigned ep = 0;

#define GATHER_SCALE(par)                                                     \
    {                                                                         \
        const int gb = tid >> 6, grp = tid & 63;                              \
        float p = 0.f;                                                        \
        _Pragma("unroll")                                                     \
        for (int m = 0; m < 4; m++)                                           \
            p += ldcg_f(&g_part[(par)][grp * 4 + m][gb]);                     \
        sPart[tid] = p;                                                       \
        __syncthreads();                                                      \
        if (tid < 8) {                                                        \
            float t = 0.f;                                                    \
            for (int g = 0; g < 64; g++) t += sPart[tid * 64 + g];            \
            sScale[tid] = CPACK * rsqrtf(fmaxf(t, 1e-30f));                   \
        }                                                                     \
        __syncthreads();                                                      \
    }

#define GRID_BAR()                                                            \
    {                                                                         \
        __syncthreads();                                                      \
        if (tid == 0) {                                                       \
            __threadfence();                                                  \
            atomicAdd(&g_bar, 1u);                                            \
            const unsigned tgt = (++ep) * 256u;                               \
            unsigned v;                                                       \
            do {                                                              \
                asm volatile("ld.global.cg.u32 %0, [%1];" : "=r"(v)           \
                             : "l"(&g_bar));                                  \
                if (v < tgt) __nanosleep(32);                                 \
            } while (v < tgt);                                                \
        } else { ++ep; }                                                      \
        __syncthreads();                                                      \
    }

    GATHER_SCALE(0);   // scale matching prep's fragments

    for (int s = 0; s < 16; s++) {
        const int src = s & 1;
        int acc0[4] = {0, 0, 0, 0};
        int acc1[4] = {0, 0, 0, 0};
        const unsigned* hb = g_hb8[src];

        if (s < 15) {  // ---- s4 mainloop: 8 k64-chunks per warp ----
            const unsigned* aBase = g_M4 + (size_t)(w * 8) * 65536 + jp * 256 + L * 8;
#pragma unroll 2
            for (int c = 0; c < 8; c++) {
                const int cg4 = w * 8 + c;
                uint2 vb0 = ldcg_u2(hb + ((2 * cg4 + 0) * 32 + L) * 2);
                uint2 vb1 = ldcg_u2(hb + ((2 * cg4 + 1) * 32 + L) * 2);
                uint4 A0, A1;
                ldg_v8_el(aBase + (size_t)c * 65536, A0, A1);
                uint4 e0 = make_uint4(sx4(A0.x & 0x0F0F0F0Fu), sx4(A0.y & 0x0F0F0F0Fu),
                                      sx4(A0.z & 0x0F0F0F0Fu), sx4(A0.w & 0x0F0F0F0Fu));
                mma_s8(acc0, e0, vb0.x, vb0.y);
                uint4 e1 = make_uint4(sx4(A1.x & 0x0F0F0F0Fu), sx4(A1.y & 0x0F0F0F0Fu),
                                      sx4(A1.z & 0x0F0F0F0Fu), sx4(A1.w & 0x0F0F0F0Fu));
                mma_s8(acc1, e1, vb0.x, vb0.y);
                uint4 o0 = make_uint4(sx4((A0.x >> 4) & 0x0F0F0F0Fu), sx4((A0.y >> 4) & 0x0F0F0F0Fu),
                                      sx4((A0.z >> 4) & 0x0F0F0F0Fu), sx4((A0.w >> 4) & 0x0F0F0F0Fu));
                mma_s8(acc0, o0, vb1.x, vb1.y);
                uint4 o1 = make_uint4(sx4((A1.x >> 4) & 0x0F0F0F0Fu), sx4((A1.y >> 4) & 0x0F0F0F0Fu),
                                      sx4((A1.z >> 4) & 0x0F0F0F0Fu), sx4((A1.w >> 4) & 0x0F0F0F0Fu));
                mma_s8(acc1, o1, vb1.x, vb1.y);
            }
        } else {       // ---- s8 mainloop (final step): 16 k32-chunks per warp ----
#pragma unroll 2
            for (int c = 0; c < 16; c++) {
                const int cg = w * 16 + c;
                uint2 vb = ldcg_u2(hb + (cg * 32 + L) * 2);
                uint4 a0, a1;
                ldg_v8_el(g_M8 + (size_t)cg * 65536 + jp * 256 + L * 8, a0, a1);
                mma_s8(acc0, a0, vb.x, vb.y);
                mma_s8(acc1, a1, vb.x, vb.y);
            }
        }

        // ---- split-K (verified D-frag map) ----
        __syncthreads();
        {
            int* rw = redH + w * 256;
            const int b0 = 2 * (L & 3);
            const int jl = L >> 2;
            rw[(b0 + 0) * 32 + jl]      = acc0[0];
            rw[(b0 + 1) * 32 + jl]      = acc0[1];
            rw[(b0 + 0) * 32 + jl + 8]  = acc0[2];
            rw[(b0 + 1) * 32 + jl + 8]  = acc0[3];
            rw[(b0 + 0) * 32 + jl + 16] = acc1[0];
            rw[(b0 + 1) * 32 + jl + 16] = acc1[1];
            rw[(b0 + 0) * 32 + jl + 24] = acc1[2];
            rw[(b0 + 1) * 32 + jl + 24] = acc1[3];
        }
        __syncthreads();

        // ---- epilogue: 256 threads = 32 j x 8 b (warp == one b) ----
        float val = 0.f;
        if (tid < 256) {
            const int j_l = tid & 31;
            const int b   = tid >> 5;
            int hsum = 0;
#pragma unroll
            for (int ww = 0; ww < 16; ww++) hsum += redH[ww * 256 + b * 32 + j_l];

            const int   qz  = ldcg_i(&g_sums16[s][b]);
            const float dot = (s < 15)
                ? (16.f * (float)hsum + 127.f * (float)qz) * (1.f / 255.f)
                : ((float)hsum + 127.5f * (float)qz) * (1.f / 255.f);

            const int j = jb + j_l;
            const float dec = (s == 0) ? hs_in[j] : g_u[src][(size_t)b * D + j];
            float preq = fmaf(0.5f * sScale[b], dec, dot);
            val = (preq >= 0.f) ? preq : 0.01f * preq;   // leaky (scale>0 commutes)
            val *= (1.0f / CPACK);
            g_u[src ^ 1][(size_t)b * D + j] = val;

            float v2 = val * val;
#pragma unroll
            for (int o = 16; o; o >>= 1) v2 += __shfl_down_sync(0xFFFFFFFFu, v2, o);
            if (L == 0) g_part[src ^ 1][jp][b] = v2;
        }
        if (s == 15) break;

        GRID_BAR();                 // all g_part / g_u writes visible
        GATHER_SCALE(src ^ 1);      // exact next-step scale, fixed order

        if (tid < 256) {            // quantize register-resident val
            const int j_l = tid & 31;
            const int b   = tid >> 5;
            const int j   = jb + j_l;
            int q = __float2int_rn(val * sScale[b]);
            q = max(-127, min(127, q));
            const int word = (j >> 5) * 64 + b * 8 + ((j >> 2) & 3) * 2 + ((j >> 4) & 1);
            reinterpret_cast<char*>(g_hb8[src ^ 1])[word * 4 + (j & 3)] = (char)q;

            int qs = q;
#pragma unroll
            for (int o = 16; o; o >>= 1) qs += __shfl_down_sync(0xFFFFFFFFu, qs, o);
            if (L == 0) atomicAdd(&g_sums16[s + 1][b], qs);
        }
        GRID_BAR();                 // fragments + sums visible for next step
    }
#undef GATHER_SCALE
#undef GRID_BAR
}

// ---------------------------------------------------------------------------
// Final L2 normalize of g_u[0] rows into the external output.
// ---------------------------------------------------------------------------
__global__ void norm_kernel(float* __restrict__ out) {
    const int b = blockIdx.x, tid = threadIdx.x;  // 8 x 256
    __shared__ float red[8];
    __shared__ float s_inv;
    const float* __restrict__ u = &g_u[0][(size_t)b * D];

    float ss = 0.f;
    for (int i = tid; i < D; i += 256) { float v = u[i]; ss = fmaf(v, v, ss); }
#pragma unroll
    for (int o = 16; o; o >>= 1) ss += __shfl_down_sync(0xFFFFFFFFu, ss, o);
    if ((tid & 31) == 0) red[tid >> 5] = ss;
    __syncthreads();
    if (tid == 0) {
        float v = 0.f;
#pragma unroll
        for (int w = 0; w < 8; w++) v += red[w];
        s_inv = 1.0f / fmaxf(sqrtf(v), 1e-12f);
    }
    __syncthreads();
    const float inv = s_inv;
    for (int i = tid; i < D; i += 256) out[b * D + i] = u[i] * inv;
}

// ---------------------------------------------------------------------------
extern "C" void kernel_launch(void* const* d_in, const int* in_sizes, int n_in,
                              void* d_out, int out_size) {
    const float* x  = (const float*)d_in[0];   // (8, 8192)
    const float* M  = (const float*)d_in[1];   // (8192, 8192)
    const float* hs = (const float*)d_in[2];   // (1, 8192) zeros
    float* out = (float*)d_out;                // (8, 8192)

    convert_kernel<<<8192, 256>>>(M);          // M -> s8 + s4 fragment-linear
    prep_kernel<<<8, 256>>>(x);                // state init + fragments + bar reset
    attractor_kernel<<<NBLK, 512>>>(hs);       // all 16 steps, persistent
    norm_kernel<<<8, 256>>>(out);              // u_16 (in g_u[0]) -> normalized out
}

// round 16
// speedup vs baseline: 1.3898x; 1.3898x over previous
#include <cuda_runtime.h>
#include <cstdint>

#define D 8192
#define B 8
#define NBLK 256                     // iter blocks: 32 j-cols (one j-tile PAIR) each
#define CPACK 2262.7417f             // 25 * sqrt(8192): pack target rms = 25

// Static device scratch (no runtime allocation allowed).
__device__ __align__(128) unsigned g_M8[(size_t)D * D / 4];  // 64 MB s8 M, pair-fragment-linear
__device__ __align__(128) unsigned g_M4[(size_t)D * D / 8];  // 32 MB s4 M (nibble-packed pairs)
__device__ __align__(16) float    g_u[2][B * D];             // ping-pong fp32 state
__device__ __align__(16) float    g_part[2][NBLK][B];        // per-block row sum(val^2)
__device__ __align__(16) unsigned g_hb8[(D / 32) * 64];      // 64 KB: h s8 B-fragments
__device__ float g_scale[B];                                 // per-row pack scale s_b
__device__ int   g_sums[2][B];                               // per-row sum of q_h (dbl-buffered)

// ---------------------------------------------------------------------------
// Primitives
// ---------------------------------------------------------------------------
__device__ __forceinline__ void mma_s8(int* d, const uint4& a, unsigned b0, unsigned b1) {
    asm volatile(
        "mma.sync.aligned.m16n8k32.row.col.s32.s8.s8.s32 "
        "{%0,%1,%2,%3},{%4,%5,%6,%7},{%8,%9},{%0,%1,%2,%3};"
        : "+r"(d[0]), "+r"(d[1]), "+r"(d[2]), "+r"(d[3])
        : "r"(a.x), "r"(a.y), "r"(a.z), "r"(a.w), "r"(b0), "r"(b1));
}
__device__ __forceinline__ void ldg_v8_el(const unsigned* p, uint4& a, uint4& b) {
    asm volatile(
        "ld.global.nc.L2::evict_last.v8.b32 {%0,%1,%2,%3,%4,%5,%6,%7}, [%8];"
        : "=r"(a.x), "=r"(a.y), "=r"(a.z), "=r"(a.w),
          "=r"(b.x), "=r"(b.y), "=r"(b.z), "=r"(b.w) : "l"(p));
}
__device__ __forceinline__ unsigned sx4(unsigned t) {        // nibble sign-extend
    return __vsub4(t ^ 0x08080808u, 0x08080808u);
}
__device__ __forceinline__ unsigned pack_nib(unsigned a, unsigned b) {
    unsigned ta = __vaddss4(a, 0x08080808u);
    unsigned tb = __vaddss4(b, 0x08080808u);
    return ((ta >> 4) & 0x0F0F0F0Fu) | (tb & 0xF0F0F0F0u);
}

// ---------------------------------------------------------------------------
// One-time fused convert (validated in R15): M fp32 -> s8 pair-fragment-linear
// AND nibble-packed s4, one pass. Block = one cg-PAIR (64 i) x 128 j.
// Word layout (verified R7..R15): W(cg, jt, L, r) = cg*65536 + (jt>>1)*256 +
// L*8 + (jt&1)*4 + r. s4 word (cg4=cg/2) packs (even cg lo, odd cg hi).
// ---------------------------------------------------------------------------
__global__ void convert_kernel(const float* __restrict__ M) {
    __shared__ char     tq[64 * 128];
    __shared__ unsigned sW[2][1024];
    const int tid = threadIdx.x;                 // 256
    const int cp  = blockIdx.x & 127;            // cg-pair 0..127
    const int bj  = blockIdx.x >> 7;             // j-super 0..63 (128 j each)
    const int i0  = cp * 64, j0 = bj * 128;

    const float4* M4p = (const float4*)M;
#pragma unroll
    for (int rep = 0; rep < 8; rep++) {
        int idx = rep * 256 + tid;               // 2048 float4 = 64 x 128 floats
        int r = idx >> 5, c4 = idx & 31;
        float4 v = M4p[(size_t)(i0 + r) * (D / 4) + (j0 >> 2) + c4];
        float vv[4] = {v.x, v.y, v.z, v.w};
#pragma unroll
        for (int e = 0; e < 4; e++) {
            int q = __float2int_rn(fmaf(vv[e], 255.f, -127.5f));
            q = max(-128, min(127, q));
            tq[r * 128 + c4 * 4 + e] = (char)q;
        }
    }
    __syncthreads();

#pragma unroll
    for (int wrep = 0; wrep < 8; wrep++) {
        int widx = wrep * 256 + tid;             // 2048 s8 words (2 cg x 1024)
        int cgl = widx >> 10;
        int wi2 = widx & 1023;
        int tl = wi2 >> 7, wi = wi2 & 127;
        int Lq = wi >> 2, rq = wi & 3;
        int jloc = (Lq >> 2) + 8 * (rq & 1);
        int kb   = 4 * (Lq & 3) + 16 * (rq >> 1) + cgl * 32;
        unsigned wd = ((unsigned char)tq[(kb + 0) * 128 + tl * 16 + jloc])
                    | ((unsigned char)tq[(kb + 1) * 128 + tl * 16 + jloc] << 8)
                    | ((unsigned char)tq[(kb + 2) * 128 + tl * 16 + jloc] << 16)
                    | ((unsigned char)tq[(kb + 3) * 128 + tl * 16 + jloc] << 24);
        int jt = bj * 8 + tl;
        size_t off = (size_t)(jt >> 1) * 256 + Lq * 8 + (jt & 1) * 4 + rq;
        g_M8[(size_t)(cp * 2 + cgl) * 65536 + off] = wd;
        sW[cgl][tl * 128 + wi] = wd;
    }
    __syncthreads();

#pragma unroll
    for (int wrep = 0; wrep < 4; wrep++) {
        int widx = wrep * 256 + tid;             // 1024 s4 words
        int tl = widx >> 7, wi = widx & 127;
        int Lq = wi >> 2, rq = wi & 3;
        int jt = bj * 8 + tl;
        size_t off = (size_t)(jt >> 1) * 256 + Lq * 8 + (jt & 1) * 4 + rq;
        g_M4[(size_t)cp * 65536 + off] =
            pack_nib(sW[0][tl * 128 + wi], sW[1][tl * 128 + wi]);
    }
}

// ---------------------------------------------------------------------------
// One-time: copy x -> g_u[0]; ||x_b||^2 -> g_part[0][0][b]; zero g_sums[0].
// ---------------------------------------------------------------------------
__global__ void prep_kernel(const float* __restrict__ x) {
    const int b = blockIdx.x, tid = threadIdx.x;  // 8 blocks x 256
    __shared__ float red[8];
    float ss = 0.f;
    for (int i = tid; i < D; i += 256) {
        float v = x[b * D + i];
        g_u[0][b * D + i] = v;
        ss = fmaf(v, v, ss);
    }
#pragma unroll
    for (int o = 16; o; o >>= 1) ss += __shfl_down_sync(0xFFFFFFFFu, ss, o);
    if ((tid & 31) == 0) red[tid >> 5] = ss;
    __syncthreads();
    if (tid == 0) {
        float tot = 0.f;
#pragma unroll
        for (int w = 0; w < 8; w++) tot += red[w];
        red[0] = tot;
        g_sums[0][b] = 0;
    }
    __syncthreads();
    g_part[0][tid][b] = (tid == 0) ? red[0] : 0.f;   // 256 partial slots
}

// ---------------------------------------------------------------------------
// Per-iteration pack (grid 64 = 8 rows x 8 segments, 256 threads):
// s_b = CPACK/||u_b||; quantize h -> s8 B-fragments; exact zero-point sums
// via integer atomicAdd (order-independent => deterministic). Word layout
// (verified): element i -> word (i>>5)*64 + b*8 + ((i>>2)&3)*2 + ((i>>4)&1).
// ---------------------------------------------------------------------------
__global__ void pack_kernel(int src) {
    const int b   = blockIdx.x >> 3;
    const int seg = blockIdx.x & 7;
    const int tid = threadIdx.x;                  // 256
    __shared__ float sred[8];
    __shared__ float s_sh;
    __shared__ int   ired[8];

    float ps = g_part[src][tid][b];               // 256 block-partials
#pragma unroll
    for (int o = 16; o; o >>= 1) ps += __shfl_down_sync(0xFFFFFFFFu, ps, o);
    if ((tid & 31) == 0) sred[tid >> 5] = ps;
    __syncthreads();
    if (tid == 0) {
        float t = 0.f;
#pragma unroll
        for (int w = 0; w < 8; w++) t += sred[w];
        s_sh = CPACK * rsqrtf(fmaxf(t, 1e-30f));
        if (seg == 0) g_scale[b] = s_sh;
    }
    __syncthreads();
    const float s = s_sh;

    const int i0 = seg * 1024 + tid * 4;
    float4 v = ((const float4*)(g_u[src] + (size_t)b * D))[i0 >> 2];
    float vv[4] = {v.x, v.y, v.z, v.w};
    unsigned wd = 0;
    int qsum = 0;
#pragma unroll
    for (int e = 0; e < 4; e++) {
        int q = __float2int_rn(vv[e] * s);
        q = max(-127, min(127, q));
        qsum += q;
        wd |= (unsigned)(q & 255) << (8 * e);
    }
    const int word = (i0 >> 5) * 64 + b * 8 + ((i0 >> 2) & 3) * 2 + ((i0 >> 4) & 1);
    g_hb8[word] = wd;

#pragma unroll
    for (int o = 16; o; o >>= 1) qsum += __shfl_down_sync(0xFFFFFFFFu, qsum, o);
    if ((tid & 31) == 0) ired[tid >> 5] = qsum;
    __syncthreads();
    if (tid == 0) {
        int t = 0;
#pragma unroll
        for (int w = 0; w < 8; w++) t += ired[w];
        atomicAdd(&g_sums[src][b], t);
    }
}

// ---------------------------------------------------------------------------
// s4-M step (iterations 0..14): u_next = leaky(0.5*s_b*dec + s_b*(u@M))/CPACK
//   s_b*dot_j = [ 16*Σ q_h*q4 + 127*Σ q_h ] / 255
// Grid 256 x 1024 thr (32 warps, 2 CTAs/SM — R12's proven occupancy): warp w
// covers 4 k64-chunks: 1 v8 nibble load -> in-register expansion to verified
// s8 A-fragments -> 4 s8 mmas. Half the M traffic of the s8 path at the SAME
// occupancy (R14's s4 was latency-bound at 512 thr; this fixes that).
// ---------------------------------------------------------------------------
template <bool FIRST>
__global__ void __launch_bounds__(1024, 2)
iter4_kernel(const float* __restrict__ hs_in, int src) {
    __shared__ int   redH[32 * 256];   // 32 KB split-K buffer
    __shared__ float arr_out[8];
    const int tid = threadIdx.x;
    const int L   = tid & 31;
    const int w   = tid >> 5;          // 0..31
    const int jp  = blockIdx.x;        // j-tile pair 0..255
    const int jb  = jp * 32;

    if (blockIdx.x == 0 && tid < B) g_sums[src ^ 1][tid] = 0;

    int acc0[4] = {0, 0, 0, 0};
    int acc1[4] = {0, 0, 0, 0};
    const uint2* bH = (const uint2*)g_hb8;
    const unsigned* aBase = g_M4 + (size_t)(w * 4) * 65536 + jp * 256 + L * 8;

#pragma unroll
    for (int c = 0; c < 4; c++) {
        const int cg4 = w * 4 + c;                       // k64-chunk
        uint2 vb0 = __ldg(&bH[(2 * cg4 + 0) * 32 + L]);
        uint2 vb1 = __ldg(&bH[(2 * cg4 + 1) * 32 + L]);
        uint4 A0, A1;
        ldg_v8_el(aBase + (size_t)c * 65536, A0, A1);

        uint4 e0 = make_uint4(sx4(A0.x & 0x0F0F0F0Fu), sx4(A0.y & 0x0F0F0F0Fu),
                              sx4(A0.z & 0x0F0F0F0Fu), sx4(A0.w & 0x0F0F0F0Fu));
        mma_s8(acc0, e0, vb0.x, vb0.y);
        uint4 e1 = make_uint4(sx4(A1.x & 0x0F0F0F0Fu), sx4(A1.y & 0x0F0F0F0Fu),
                              sx4(A1.z & 0x0F0F0F0Fu), sx4(A1.w & 0x0F0F0F0Fu));
        mma_s8(acc1, e1, vb0.x, vb0.y);
        uint4 o0 = make_uint4(sx4((A0.x >> 4) & 0x0F0F0F0Fu), sx4((A0.y >> 4) & 0x0F0F0F0Fu),
                              sx4((A0.z >> 4) & 0x0F0F0F0Fu), sx4((A0.w >> 4) & 0x0F0F0F0Fu));
        mma_s8(acc0, o0, vb1.x, vb1.y);
        uint4 o1 = make_uint4(sx4((A1.x >> 4) & 0x0F0F0F0Fu), sx4((A1.y >> 4) & 0x0F0F0F0Fu),
                              sx4((A1.z >> 4) & 0x0F0F0F0Fu), sx4((A1.w >> 4) & 0x0F0F0F0Fu));
        mma_s8(acc1, o1, vb1.x, vb1.y);
    }

    // split-K: D-frag (j_l = (L>>2) [+8], b = 2*(L&3) [+1]); odd tile at +16
    {
        int* rw = redH + w * 256;                        // [b*32 + j_l]
        const int b0 = 2 * (L & 3);
        const int jl = L >> 2;
        rw[(b0 + 0) * 32 + jl]          = acc0[0];
        rw[(b0 + 1) * 32 + jl]          = acc0[1];
        rw[(b0 + 0) * 32 + jl + 8]      = acc0[2];
        rw[(b0 + 1) * 32 + jl + 8]      = acc0[3];
        rw[(b0 + 0) * 32 + jl + 16]     = acc1[0];
        rw[(b0 + 1) * 32 + jl + 16]     = acc1[1];
        rw[(b0 + 0) * 32 + jl + 24]     = acc1[2];
        rw[(b0 + 1) * 32 + jl + 24]     = acc1[3];
    }
    __syncthreads();

    // epilogue: 256 threads = 32 j x 8 b (warp == one b row)
    if (tid < 256) {
        const int j_l = tid & 31;
        const int b   = tid >> 5;
        int hsum = 0;
#pragma unroll
        for (int ww = 0; ww < 32; ww++) hsum += redH[ww * 256 + b * 32 + j_l];

        const float s_b = g_scale[b];
        const float dot = (16.f * (float)hsum + 127.f * (float)g_sums[src][b]) * (1.f / 255.f);

        const int j = jb + j_l;
        const float dec = FIRST ? hs_in[j] : g_u[src][(size_t)b * D + j];
        float preq = fmaf(0.5f * s_b, dec, dot);
        float val  = (preq >= 0.f) ? preq : 0.01f * preq;   // leaky (scale>0 commutes)
        val *= (1.0f / CPACK);
        g_u[src ^ 1][(size_t)b * D + j] = val;

        float v2 = val * val;                  // full warp shares one b
#pragma unroll
        for (int o = 16; o; o >>= 1) v2 += __shfl_down_sync(0xFFFFFFFFu, v2, o);
        if (L == 0) arr_out[b] = v2;
    }
    __syncthreads();
    if (tid < B)
        g_part[src ^ 1][blockIdx.x][tid] = arr_out[tid];
}

// ---------------------------------------------------------------------------
// Full-precision s8 step (iteration 15) — R12's verified kernel:
//   s_b*dot_j = [ Σ q_h*q_m + 127.5*Σ q_h ] / 255
// Grid 256 x 1024 thr (32 warps, 2 CTAs/SM).
// ---------------------------------------------------------------------------
__global__ void __launch_bounds__(1024, 2)
iter8_kernel(const float* __restrict__ hs_in, int src) {
    __shared__ int   redH[32 * 256];   // 32 KB split-K buffer
    __shared__ float arr_out[8];
    const int tid = threadIdx.x;
    const int L   = tid & 31;
    const int w   = tid >> 5;             // 0..31
    const int jp  = blockIdx.x;           // j-tile pair 0..255
    const int jb  = jp * 32;

    if (blockIdx.x == 0 && tid < B) g_sums[src ^ 1][tid] = 0;

    int acc0[4] = {0, 0, 0, 0};
    int acc1[4] = {0, 0, 0, 0};
    const uint2* bH = (const uint2*)g_hb8;

#pragma unroll
    for (int c = 0; c < 8; c++) {
        const int cg = w * 8 + c;                        // k32-chunk
        uint2 vb = __ldg(&bH[cg * 32 + L]);
        uint4 a0, a1;
        ldg_v8_el(g_M8 + (size_t)cg * 65536 + jp * 256 + L * 8, a0, a1);
        mma_s8(acc0, a0, vb.x, vb.y);
        mma_s8(acc1, a1, vb.x, vb.y);
    }

    {
        int* rw = redH + w * 256;                        // [b*32 + j_l]
        const int b0 = 2 * (L & 3);
        const int jl = L >> 2;
        rw[(b0 + 0) * 32 + jl]          = acc0[0];
        rw[(b0 + 1) * 32 + jl]          = acc0[1];
        rw[(b0 + 0) * 32 + jl + 8]      = acc0[2];
        rw[(b0 + 1) * 32 + jl + 8]      = acc0[3];
        rw[(b0 + 0) * 32 + jl + 16]     = acc1[0];
        rw[(b0 + 1) * 32 + jl + 16]     = acc1[1];
        rw[(b0 + 0) * 32 + jl + 24]     = acc1[2];
        rw[(b0 + 1) * 32 + jl + 24]     = acc1[3];
    }
    __syncthreads();

    if (tid < 256) {
        const int j_l = tid & 31;
        const int b   = tid >> 5;
        int hsum = 0;
#pragma unroll
        for (int ww = 0; ww < 32; ww++) hsum += redH[ww * 256 + b * 32 + j_l];

        const float s_b = g_scale[b];
        const float dot = ((float)hsum + 127.5f * (float)g_sums[src][b]) * (1.f / 255.f);

        const int j = jb + j_l;
        const float dec = g_u[src][(size_t)b * D + j];
        float preq = fmaf(0.5f * s_b, dec, dot);
        float val  = (preq >= 0.f) ? preq : 0.01f * preq;
        val *= (1.0f / CPACK);
        g_u[src ^ 1][(size_t)b * D + j] = val;

        float v2 = val * val;
#pragma unroll
        for (int o = 16; o; o >>= 1) v2 += __shfl_down_sync(0xFFFFFFFFu, v2, o);
        if (L == 0) arr_out[b] = v2;
    }
    __syncthreads();
    if (tid < B)
        g_part[src ^ 1][blockIdx.x][tid] = arr_out[tid];
}

// ---------------------------------------------------------------------------
// Final L2 normalize of g_u[0] rows into the external output.
// ---------------------------------------------------------------------------
__global__ void norm_kernel(float* __restrict__ out) {
    const int b = blockIdx.x, tid = threadIdx.x;  // 8 x 256
    __shared__ float red[8];
    __shared__ float s_inv;
    const float* __restrict__ u = &g_u[0][(size_t)b * D];

    float ss = 0.f;
    for (int i = tid; i < D; i += 256) { float v = u[i]; ss = fmaf(v, v, ss); }
#pragma unroll
    for (int o = 16; o; o >>= 1) ss += __shfl_down_sync(0xFFFFFFFFu, ss, o);
    if ((tid & 31) == 0) red[tid >> 5] = ss;
    __syncthreads();
    if (tid == 0) {
        float v = 0.f;
#pragma unroll
        for (int w = 0; w < 8; w++) v += red[w];
        s_inv = 1.0f / fmaxf(sqrtf(v), 1e-12f);
    }
    __syncthreads();
    const float inv = s_inv;
    for (int i = tid; i < D; i += 256) out[b * D + i] = u[i] * inv;
}

// ---------------------------------------------------------------------------
extern "C" void kernel_launch(void* const* d_in, const int* in_sizes, int n_in,
                              void* d_out, int out_size) {
    const float* x  = (const float*)d_in[0];   // (8, 8192)
    const float* M  = (const float*)d_in[1];   // (8192, 8192)
    const float* hs = (const float*)d_in[2];   // (1, 8192) zeros
    float* out = (float*)d_out;                // (8, 8192)

    convert_kernel<<<8192, 256>>>(M);          // M -> s8 + s4 fragment-linear (one pass)
    prep_kernel<<<8, 256>>>(x);                // x -> g_u[0], norms, zero g_sums[0]

    // Steps 0..14 on 4-bit M (errors contracted by the attractor);
    // step 15 on full 8-bit M to restore precision.
    for (int t = 0; t < 16; ++t) {
        pack_kernel<<<64, 256>>>(t & 1);
        if (t == 0)      iter4_kernel<true><<<NBLK, 1024>>>(hs, 0);
        else if (t < 15) iter4_kernel<false><<<NBLK, 1024>>>(hs, t & 1);
        else             iter8_kernel<<<NBLK, 1024>>>(hs, t & 1);
    }

    // u_16 lives in g_u[0]; one final normalize
    norm_kernel<<<8, 256>>>(out);
}

// round 17
// speedup vs baseline: 1.4438x; 1.0389x over previous
#include <cuda_runtime.h>
#include <cstdint>

#define D 8192
#define B 8
#define NBLK 256                     // iter blocks: 32 j-cols (one j-tile PAIR) each
#define CPACK 2262.7417f             // 25 * sqrt(8192): pack target rms = 25

// Static device scratch (no runtime allocation allowed).
__device__ __align__(128) unsigned g_M8[(size_t)D * D / 4];  // 64 MB s8 M, pair-fragment-linear
__device__ __align__(128) unsigned g_M4[(size_t)D * D / 8];  // 32 MB M as BIASED nibbles (q4+8)
__device__ __align__(16) float    g_u[2][B * D];             // ping-pong fp32 state
__device__ __align__(16) float    g_part[2][NBLK][B];        // per-block row sum(val^2)
__device__ __align__(16) unsigned g_hb8[(D / 32) * 64];      // 64 KB: h s8 B-fragments (pair-interleaved)
__device__ float g_scale[B];                                 // per-row pack scale s_b
__device__ int   g_sums[2][B];                               // per-row sum of q_h (dbl-buffered)

// ---------------------------------------------------------------------------
// Primitives
// ---------------------------------------------------------------------------
__device__ __forceinline__ void mma_s8(int* d, const uint4& a, unsigned b0, unsigned b1) {
    asm volatile(
        "mma.sync.aligned.m16n8k32.row.col.s32.s8.s8.s32 "
        "{%0,%1,%2,%3},{%4,%5,%6,%7},{%8,%9},{%0,%1,%2,%3};"
        : "+r"(d[0]), "+r"(d[1]), "+r"(d[2]), "+r"(d[3])
        : "r"(a.x), "r"(a.y), "r"(a.z), "r"(a.w), "r"(b0), "r"(b1));
}
// Mixed signedness: A unsigned (biased nibbles n'=q4+8), B signed (q_h).
__device__ __forceinline__ void mma_u8s8(int* d, const uint4& a, unsigned b0, unsigned b1) {
    asm volatile(
        "mma.sync.aligned.m16n8k32.row.col.s32.u8.s8.s32 "
        "{%0,%1,%2,%3},{%4,%5,%6,%7},{%8,%9},{%0,%1,%2,%3};"
        : "+r"(d[0]), "+r"(d[1]), "+r"(d[2]), "+r"(d[3])
        : "r"(a.x), "r"(a.y), "r"(a.z), "r"(a.w), "r"(b0), "r"(b1));
}
__device__ __forceinline__ void ldg_v8_el(const unsigned* p, uint4& a, uint4& b) {
    asm volatile(
        "ld.global.nc.L2::evict_last.v8.b32 {%0,%1,%2,%3,%4,%5,%6,%7}, [%8];"
        : "=r"(a.x), "=r"(a.y), "=r"(a.z), "=r"(a.w),
          "=r"(b.x), "=r"(b.y), "=r"(b.z), "=r"(b.w) : "l"(p));
}
// BIASED nibble pack: old encoding stored q4 mod 16; XOR 0x88888888 flips each
// nibble's top bit so the stored value is n' = q4 + 8 in [0,15] (unsigned),
// consumable by mma.u8 with a pure AND/SHF extraction (no sign-extension).
__device__ __forceinline__ unsigned pack_nib(unsigned a, unsigned b) {
    unsigned ta = __vaddss4(a, 0x08080808u);
    unsigned tb = __vaddss4(b, 0x08080808u);
    return (((ta >> 4) & 0x0F0F0F0Fu) | (tb & 0xF0F0F0F0u)) ^ 0x88888888u;
}

// ---------------------------------------------------------------------------
// One-time fused convert: M fp32 -> s8 pair-fragment-linear (verified R7..R16)
// AND biased-nibble s4, one pass. Block = one cg-PAIR (64 i) x 128 j.
// Word layout: W(cg, jt, L, r) = cg*65536 + (jt>>1)*256 + L*8 + (jt&1)*4 + r.
// ---------------------------------------------------------------------------
__global__ void convert_kernel(const float* __restrict__ M) {
    __shared__ char     tq[64 * 128];
    __shared__ unsigned sW[2][1024];
    const int tid = threadIdx.x;                 // 256
    const int cp  = blockIdx.x & 127;            // cg-pair 0..127
    const int bj  = blockIdx.x >> 7;             // j-super 0..63 (128 j each)
    const int i0  = cp * 64, j0 = bj * 128;

    const float4* M4p = (const float4*)M;
#pragma unroll
    for (int rep = 0; rep < 8; rep++) {
        int idx = rep * 256 + tid;               // 2048 float4 = 64 x 128 floats
        int r = idx >> 5, c4 = idx & 31;
        float4 v = M4p[(size_t)(i0 + r) * (D / 4) + (j0 >> 2) + c4];
        float vv[4] = {v.x, v.y, v.z, v.w};
#pragma unroll
        for (int e = 0; e < 4; e++) {
            int q = __float2int_rn(fmaf(vv[e], 255.f, -127.5f));
            q = max(-128, min(127, q));
            tq[r * 128 + c4 * 4 + e] = (char)q;
        }
    }
    __syncthreads();

#pragma unroll
    for (int wrep = 0; wrep < 8; wrep++) {
        int widx = wrep * 256 + tid;             // 2048 s8 words (2 cg x 1024)
        int cgl = widx >> 10;
        int wi2 = widx & 1023;
        int tl = wi2 >> 7, wi = wi2 & 127;
        int Lq = wi >> 2, rq = wi & 3;
        int jloc = (Lq >> 2) + 8 * (rq & 1);
        int kb   = 4 * (Lq & 3) + 16 * (rq >> 1) + cgl * 32;
        unsigned wd = ((unsigned char)tq[(kb + 0) * 128 + tl * 16 + jloc])
                    | ((unsigned char)tq[(kb + 1) * 128 + tl * 16 + jloc] << 8)
                    | ((unsigned char)tq[(kb + 2) * 128 + tl * 16 + jloc] << 16)
                    | ((unsigned char)tq[(kb + 3) * 128 + tl * 16 + jloc] << 24);
        int jt = bj * 8 + tl;
        size_t off = (size_t)(jt >> 1) * 256 + Lq * 8 + (jt & 1) * 4 + rq;
        g_M8[(size_t)(cp * 2 + cgl) * 65536 + off] = wd;
        sW[cgl][tl * 128 + wi] = wd;
    }
    __syncthreads();

#pragma unroll
    for (int wrep = 0; wrep < 4; wrep++) {
        int widx = wrep * 256 + tid;             // 1024 s4 words
        int tl = widx >> 7, wi = widx & 127;
        int Lq = wi >> 2, rq = wi & 3;
        int jt = bj * 8 + tl;
        size_t off = (size_t)(jt >> 1) * 256 + Lq * 8 + (jt & 1) * 4 + rq;
        g_M4[(size_t)cp * 65536 + off] =
            pack_nib(sW[0][tl * 128 + wi], sW[1][tl * 128 + wi]);
    }
}

// ---------------------------------------------------------------------------
// One-time: copy x -> g_u[0]; ||x_b||^2 -> g_part[0][0][b]; zero g_sums[0].
// ---------------------------------------------------------------------------
__global__ void prep_kernel(const float* __restrict__ x) {
    const int b = blockIdx.x, tid = threadIdx.x;  // 8 blocks x 256
    __shared__ float red[8];
    float ss = 0.f;
    for (int i = tid; i < D; i += 256) {
        float v = x[b * D + i];
        g_u[0][b * D + i] = v;
        ss = fmaf(v, v, ss);
    }
#pragma unroll
    for (int o = 16; o; o >>= 1) ss += __shfl_down_sync(0xFFFFFFFFu, ss, o);
    if ((tid & 31) == 0) red[tid >> 5] = ss;
    __syncthreads();
    if (tid == 0) {
        float tot = 0.f;
#pragma unroll
        for (int w = 0; w < 8; w++) tot += red[w];
        red[0] = tot;
        g_sums[0][b] = 0;
    }
    __syncthreads();
    g_part[0][tid][b] = (tid == 0) ? red[0] : 0.f;   // 256 partial slots
}

// ---------------------------------------------------------------------------
// Per-iteration pack (grid 64 = 8 rows x 8 segments, 256 threads):
// s_b = CPACK/||u_b||; quantize h -> s8 B-fragments (PAIR-INTERLEAVED:
// element i -> word (i>>6)*128 + (b*4 + ((i>>2)&3))*4 + ((i>>5)&1)*2 +
// ((i>>4)&1), byte i&3 — so one uint4 covers both k32-halves of a k64 chunk);
// exact zero-point sums via integer atomicAdd. The u float4 load is issued
// BEFORE the partial-norm gather so the two memory round-trips overlap.
// ---------------------------------------------------------------------------
__global__ void pack_kernel(int src) {
    const int b   = blockIdx.x >> 3;
    const int seg = blockIdx.x & 7;
    const int tid = threadIdx.x;                  // 256
    __shared__ float sred[8];
    __shared__ float s_sh;
    __shared__ int   ired[8];

    // independent u load first (overlaps the partial gather below)
    const int i0 = seg * 1024 + tid * 4;
    float4 v = ((const float4*)(g_u[src] + (size_t)b * D))[i0 >> 2];

    float ps = g_part[src][tid][b];               // 256 block-partials
#pragma unroll
    for (int o = 16; o; o >>= 1) ps += __shfl_down_sync(0xFFFFFFFFu, ps, o);
    if ((tid & 31) == 0) sred[tid >> 5] = ps;
    __syncthreads();
    if (tid == 0) {
        float t = 0.f;
#pragma unroll
        for (int w = 0; w < 8; w++) t += sred[w];
        s_sh = CPACK * rsqrtf(fmaxf(t, 1e-30f));
        if (seg == 0) g_scale[b] = s_sh;
    }
    __syncthreads();
    const float s = s_sh;

    float vv[4] = {v.x, v.y, v.z, v.w};
    unsigned wd = 0;
    int qsum = 0;
#pragma unroll
    for (int e = 0; e < 4; e++) {
        int q = __float2int_rn(vv[e] * s);
        q = max(-127, min(127, q));
        qsum += q;
        wd |= (unsigned)(q & 255) << (8 * e);
    }
    const int word = (i0 >> 6) * 128 + (b * 4 + ((i0 >> 2) & 3)) * 4
                   + ((i0 >> 5) & 1) * 2 + ((i0 >> 4) & 1);
    g_hb8[word] = wd;

#pragma unroll
    for (int o = 16; o; o >>= 1) qsum += __shfl_down_sync(0xFFFFFFFFu, qsum, o);
    if ((tid & 31) == 0) ired[tid >> 5] = qsum;
    __syncthreads();
    if (tid == 0) {
        int t = 0;
#pragma unroll
        for (int w = 0; w < 8; w++) t += ired[w];
        atomicAdd(&g_sums[src][b], t);
    }
}

// ---------------------------------------------------------------------------
// s4-M step (iterations 0..14): u_next = leaky(0.5*s_b*dec + s_b*(u@M))/CPACK
// Biased-nibble algebra: m = (16*q4+127)/255, stored n' = q4+8, so
//   s_b*dot_j = [ 16*Σ q_h*n' − Σ q_h ] / 255   (mma.u8.s8; bias folds into
//   the tracked zero-point sum — NO sign-extension ALU in the mainloop).
// Grid 256 x 1024 thr (32 warps, 2 CTAs/SM): warp w covers 4 k64-chunks;
// per chunk: 1 v8 A load + 1 uint4 B load + 16 AND/SHF + 4 mma.
// ---------------------------------------------------------------------------
template <bool FIRST>
__global__ void __launch_bounds__(1024, 2)
iter4_kernel(const float* __restrict__ hs_in, int src) {
    __shared__ int   redH[32 * 256];   // 32 KB split-K buffer
    __shared__ float arr_out[8];
    const int tid = threadIdx.x;
    const int L   = tid & 31;
    const int w   = tid >> 5;          // 0..31
    const int jp  = blockIdx.x;        // j-tile pair 0..255
    const int jb  = jp * 32;

    if (blockIdx.x == 0 && tid < B) g_sums[src ^ 1][tid] = 0;

    int acc0[4] = {0, 0, 0, 0};
    int acc1[4] = {0, 0, 0, 0};
    const uint4* bH4 = (const uint4*)g_hb8;
    const unsigned* aBase = g_M4 + (size_t)(w * 4) * 65536 + jp * 256 + L * 8;

#pragma unroll
    for (int c = 0; c < 4; c++) {
        const int cg4 = w * 4 + c;                       // k64-chunk
        // one uint4: {vb_even.x, vb_even.y, vb_odd.x, vb_odd.y}
        uint4 vb = __ldg(&bH4[cg4 * 32 + L]);
        uint4 A0, A1;
        ldg_v8_el(aBase + (size_t)c * 65536, A0, A1);

        // even k32 chunk: lo nibbles (already biased-unsigned)
        uint4 e0 = make_uint4(A0.x & 0x0F0F0F0Fu, A0.y & 0x0F0F0F0Fu,
                              A0.z & 0x0F0F0F0Fu, A0.w & 0x0F0F0F0Fu);
        mma_u8s8(acc0, e0, vb.x, vb.y);
        uint4 e1 = make_uint4(A1.x & 0x0F0F0F0Fu, A1.y & 0x0F0F0F0Fu,
                              A1.z & 0x0F0F0F0Fu, A1.w & 0x0F0F0F0Fu);
        mma_u8s8(acc1, e1, vb.x, vb.y);
        // odd k32 chunk: hi nibbles
        uint4 o0 = make_uint4((A0.x >> 4) & 0x0F0F0F0Fu, (A0.y >> 4) & 0x0F0F0F0Fu,
                              (A0.z >> 4) & 0x0F0F0F0Fu, (A0.w >> 4) & 0x0F0F0F0Fu);
        mma_u8s8(acc0, o0, vb.z, vb.w);
        uint4 o1 = make_uint4((A1.x >> 4) & 0x0F0F0F0Fu, (A1.y >> 4) & 0x0F0F0F0Fu,
                              (A1.z >> 4) & 0x0F0F0F0Fu, (A1.w >> 4) & 0x0F0F0F0Fu);
        mma_u8s8(acc1, o1, vb.z, vb.w);
    }

    // split-K: D-frag (j_l = (L>>2) [+8], b = 2*(L&3) [+1]); odd tile at +16
    {
        int* rw = redH + w * 256;                        // [b*32 + j_l]
        const int b0 = 2 * (L & 3);
        const int jl = L >> 2;
        rw[(b0 + 0) * 32 + jl]          = acc0[0];
        rw[(b0 + 1) * 32 + jl]          = acc0[1];
        rw[(b0 + 0) * 32 + jl + 8]      = acc0[2];
        rw[(b0 + 1) * 32 + jl + 8]      = acc0[3];
        rw[(b0 + 0) * 32 + jl + 16]     = acc1[0];
        rw[(b0 + 1) * 32 + jl + 16]     = acc1[1];
        rw[(b0 + 0) * 32 + jl + 24]     = acc1[2];
        rw[(b0 + 1) * 32 + jl + 24]     = acc1[3];
    }
    __syncthreads();

    // epilogue: 256 threads = 32 j x 8 b (warp == one b row)
    if (tid < 256) {
        const int j_l = tid & 31;
        const int b   = tid >> 5;
        int hsum = 0;
#pragma unroll
        for (int ww = 0; ww < 32; ww++) hsum += redH[ww * 256 + b * 32 + j_l];

        const float s_b = g_scale[b];
        const float dot = (16.f * (float)hsum - (float)g_sums[src][b]) * (1.f / 255.f);

        const int j = jb + j_l;
        const float dec = FIRST ? hs_in[j] : g_u[src][(size_t)b * D + j];
        float preq = fmaf(0.5f * s_b, dec, dot);
        float val  = (preq >= 0.f) ? preq : 0.01f * preq;   // leaky (scale>0 commutes)
        val *= (1.0f / CPACK);
        g_u[src ^ 1][(size_t)b * D + j] = val;

        float v2 = val * val;                  // full warp shares one b
#pragma unroll
        for (int o = 16; o; o >>= 1) v2 += __shfl_down_sync(0xFFFFFFFFu, v2, o);
        if (L == 0) arr_out[b] = v2;
    }
    __syncthreads();
    if (tid < B)
        g_part[src ^ 1][blockIdx.x][tid] = arr_out[tid];
}

// ---------------------------------------------------------------------------
// Full-precision s8 step (iteration 15) — R12's verified math; B-fragment
// index adapted to the pair-interleaved layout:
// chunk cg, lane L -> uint2 at (cg>>1)*64 + 2L + (cg&1).
// ---------------------------------------------------------------------------
__global__ void __launch_bounds__(1024, 2)
iter8_kernel(const float* __restrict__ hs_in, int src) {
    __shared__ int   redH[32 * 256];   // 32 KB split-K buffer
    __shared__ float arr_out[8];
    const int tid = threadIdx.x;
    const int L   = tid & 31;
    const int w   = tid >> 5;             // 0..31
    const int jp  = blockIdx.x;           // j-tile pair 0..255
    const int jb  = jp * 32;

    if (blockIdx.x == 0 && tid < B) g_sums[src ^ 1][tid] = 0;

    int acc0[4] = {0, 0, 0, 0};
    int acc1[4] = {0, 0, 0, 0};
    const uint2* bH = (const uint2*)g_hb8;

#pragma unroll
    for (int c = 0; c < 8; c++) {
        const int cg = w * 8 + c;                        // k32-chunk
        uint2 vb = __ldg(&bH[(cg >> 1) * 64 + 2 * L + (cg & 1)]);
        uint4 a0, a1;
        ldg_v8_el(g_M8 + (size_t)cg * 65536 + jp * 256 + L * 8, a0, a1);
        mma_s8(acc0, a0, vb.x, vb.y);
        mma_s8(acc1, a1, vb.x, vb.y);
    }

    {
        int* rw = redH + w * 256;                        // [b*32 + j_l]
        const int b0 = 2 * (L & 3);
        const int jl = L >> 2;
        rw[(b0 + 0) * 32 + jl]          = acc0[0];
        rw[(b0 + 1) * 32 + jl]          = acc0[1];
        rw[(b0 + 0) * 32 + jl + 8]      = acc0[2];
        rw[(b0 + 1) * 32 + jl + 8]      = acc0[3];
        rw[(b0 + 0) * 32 + jl + 16]     = acc1[0];
        rw[(b0 + 1) * 32 + jl + 16]     = acc1[1];
        rw[(b0 + 0) * 32 + jl + 24]     = acc1[2];
        rw[(b0 + 1) * 32 + jl + 24]     = acc1[3];
    }
    __syncthreads();

    if (tid < 256) {
        const int j_l = tid & 31;
        const int b   = tid >> 5;
        int hsum = 0;
#pragma unroll
        for (int ww = 0; ww < 32; ww++) hsum += redH[ww * 256 + b * 32 + j_l];

        const float s_b = g_scale[b];
        const float dot = ((float)hsum + 127.5f * (float)g_sums[src][b]) * (1.f / 255.f);

        const int j = jb + j_l;
        const float dec = g_u[src][(size_t)b * D + j];
        float preq = fmaf(0.5f * s_b, dec, dot);
        float val  = (preq >= 0.f) ? preq : 0.01f * preq;
        val *= (1.0f / CPACK);
        g_u[src ^ 1][(size_t)b * D + j] = val;

        float v2 = val * val;
#pragma unroll
        for (int o = 16; o; o >>= 1) v2 += __shfl_down_sync(0xFFFFFFFFu, v2, o);
        if (L == 0) arr_out[b] = v2;
    }
    __syncthreads();
    if (tid < B)
        g_part[src ^ 1][blockIdx.x][tid] = arr_out[tid];
}

// ---------------------------------------------------------------------------
// Final L2 normalize of g_u[0] rows into the external output.
// ---------------------------------------------------------------------------
__global__ void norm_kernel(float* __restrict__ out) {
    const int b = blockIdx.x, tid = threadIdx.x;  // 8 x 256
    __shared__ float red[8];
    __shared__ float s_inv;
    const float* __restrict__ u = &g_u[0][(size_t)b * D];

    float ss = 0.f;
    for (int i = tid; i < D; i += 256) { float v = u[i]; ss = fmaf(v, v, ss); }
#pragma unroll
    for (int o = 16; o; o >>= 1) ss += __shfl_down_sync(0xFFFFFFFFu, ss, o);
    if ((tid & 31) == 0) red[tid >> 5] = ss;
    __syncthreads();
    if (tid == 0) {
        float v = 0.f;
#pragma unroll
        for (int w = 0; w < 8; w++) v += red[w];
        s_inv = 1.0f / fmaxf(sqrtf(v), 1e-12f);
    }
    __syncthreads();
    const float inv = s_inv;
    for (int i = tid; i < D; i += 256) out[b * D + i] = u[i] * inv;
}

// ---------------------------------------------------------------------------
extern "C" void kernel_launch(void* const* d_in, const int* in_sizes, int n_in,
                              void* d_out, int out_size) {
    const float* x  = (const float*)d_in[0];   // (8, 8192)
    const float* M  = (const float*)d_in[1];   // (8192, 8192)
    const float* hs = (const float*)d_in[2];   // (1, 8192) zeros
    float* out = (float*)d_out;                // (8, 8192)

    convert_kernel<<<8192, 256>>>(M);          // M -> s8 + biased-s4 (one pass)
    prep_kernel<<<8, 256>>>(x);                // x -> g_u[0], norms, zero g_sums[0]

    // Steps 0..14 on 4-bit M (errors contracted by the attractor);
    // step 15 on full 8-bit M to restore precision.
    for (int t = 0; t < 16; ++t) {
        pack_kernel<<<64, 256>>>(t & 1);
        if (t == 0)      iter4_kernel<true><<<NBLK, 1024>>>(hs, 0);
        else if (t < 15) iter4_kernel<false><<<NBLK, 1024>>>(hs, t & 1);
        else             iter8_kernel<<<NBLK, 1024>>>(hs, t & 1);
    }

    // u_16 lives in g_u[0]; one final normalize
    norm_kernel<<<8, 256>>>(out);
}